// round 14
// baseline (speedup 1.0000x reference)
#include <cuda_runtime.h>
#include <cuda_fp16.h>
#include <cstdint>
#include <cstddef>

#define DIM   768
#define HEADS 12
#define HD    64
#define BATCH 16
#define SEQ   3136
#define HWIMG 56
#define M_TOTAL (BATCH * SEQ)   /* 50176 */
#define QKV_N   (3 * DIM)       /* 2304  */

// GEMM tiling (mma.sync fp16 m16n8k16): 128x128x64, 256 threads,
// warp tile 64x32, 2 CTAs/SM, 3-stage cp.async pipeline, ldmatrix fragments.
#define BM 128
#define BN 128
#define BKH 64                  /* 64 halves = 128B rows */
#define KT (DIM / BKH)          /* 12 */
#define ASZ (BM * BKH * 2)      /* 16KB */
#define BSZ (BN * BKH * 2)      /* 16KB */
#define STAGE (ASZ + BSZ)       /* 32KB */
#define NSTAGE 3
#define SMEM_DYN (NSTAGE * STAGE)   /* 96KB */

#define CSPLIT 7                /* ctx N-split: 3136 = 7 * 448 */
#define CROWS  (SEQ / CSPLIT)   /* 448 */

// ---------------- scratch (static device allocations; no cudaMalloc) -------
__device__ __half g_qkvh[(size_t)M_TOTAL * QKV_N];        // [M, 3C] fp16, activated
__device__ float  g_ctx[(size_t)BATCH * HEADS * HD * HD];
__device__ float  g_ctxp[(size_t)CSPLIT * BATCH * HEADS * HD * HD];
__device__ __half g_attnh[(size_t)BATCH * DIM * SEQ];     // attn out [B, C, N] fp16
__device__ __half g_convh[(size_t)BATCH * DIM * SEQ];     // conv out [B, C, N] fp16
__device__ __half g_convT[(size_t)M_TOTAL * DIM];         // conv out [M, C] fp16
__device__ __half g_xh[(size_t)M_TOTAL * DIM];            // x fp16 [M, K]
__device__ __half g_wqT[(size_t)QKV_N * DIM];             // qkv_w^T fp16 [N, K]
__device__ __half g_wpT[(size_t)DIM * DIM];               // proj_w^T fp16 [N, K]

// ---------------------------- PTX helpers ----------------------------------
__device__ __forceinline__ uint32_t cvta_smem(const void* p) {
    uint32_t a;
    asm("{ .reg .u64 t; cvta.to.shared.u64 t, %1; cvt.u32.u64 %0, t; }"
        : "=r"(a) : "l"(p));
    return a;
}

__device__ __forceinline__ void cp16(uint32_t dst, const void* src) {
    asm volatile("cp.async.cg.shared.global [%0], [%1], 16;"
                 :: "r"(dst), "l"(src) : "memory");
}
#define CP_COMMIT() asm volatile("cp.async.commit_group;" ::: "memory")
#define CP_WAIT1()  asm volatile("cp.async.wait_group 1;" ::: "memory")
#define CP_WAIT0()  asm volatile("cp.async.wait_group 0;" ::: "memory")

__device__ __forceinline__ void ldsm_x4(uint32_t& r0, uint32_t& r1,
                                        uint32_t& r2, uint32_t& r3, uint32_t addr) {
    asm volatile("ldmatrix.sync.aligned.m8n8.x4.shared.b16 {%0,%1,%2,%3}, [%4];"
                 : "=r"(r0), "=r"(r1), "=r"(r2), "=r"(r3) : "r"(addr));
}

__device__ __forceinline__ void mma_f16(float* c, const uint32_t* a, const uint32_t* b) {
    asm volatile(
        "mma.sync.aligned.m16n8k16.row.col.f32.f16.f16.f32 "
        "{%0,%1,%2,%3}, {%4,%5,%6,%7}, {%8,%9}, {%0,%1,%2,%3};"
        : "+f"(c[0]), "+f"(c[1]), "+f"(c[2]), "+f"(c[3])
        : "r"(a[0]), "r"(a[1]), "r"(a[2]), "r"(a[3]), "r"(b[0]), "r"(b[1]));
}

// ---------------------------------------------------------------------------
// Prepass A: x fp32 -> fp16 (half2 stores)
// ---------------------------------------------------------------------------
__global__ __launch_bounds__(256) void conv_x_f16(const float* __restrict__ in)
{
    const size_t i = (size_t)blockIdx.x * 256 + threadIdx.x;   // half2 index
    if (i < (size_t)M_TOTAL * DIM / 2) {
        float2 v = ((const float2*)in)[i];
        ((half2*)g_xh)[i] = __float22half2_rn(v);
    }
}

// Prepass B: weight fp32 [K,N] -> fp16 [N,K] (coalesced reads, half2 writes)
__global__ __launch_bounds__(256) void transpose_w_f16(
    const float* __restrict__ W, __half* __restrict__ out, int N)
{
    const int i = blockIdx.x * 256 + threadIdx.x;   // over (K/2) * N
    if (i < (DIM / 2) * N) {
        const int n = i % N, k2 = i / N;
        float a = W[(size_t)(2 * k2) * N + n];
        float b = W[(size_t)(2 * k2 + 1) * N + n];
        *(half2*)&out[(size_t)n * DIM + 2 * k2] = __floats2half2_rn(a, b);
    }
}

// ---------------------------------------------------------------------------
// fp16 GEMM core: C[M,N] = Ah[M,K] @ BhT[N,K]^T.
// A smem: [m][64 halves] 128B rows, 16B-unit swizzle j' = j ^ (m&7).
// B smem: [n][64 halves] same. Fragments via ldmatrix.x4.
// ---------------------------------------------------------------------------
#define GEMM_BODY(ASRC_EXPR, BSRC_PTR)                                        \
    extern __shared__ char smem[];                                            \
    const uint32_t sb = cvta_smem(smem);                                      \
    const int tid  = threadIdx.x;                                             \
    const int wid  = tid >> 5, lane = tid & 31;                               \
    const int gid  = lane >> 2, tig = lane & 3;                               \
    const int m0 = blockIdx.y * BM, n0 = blockIdx.x * BN;                     \
    const int wm = (wid & 1) * 64, wn = (wid >> 1) * 32;                      \
    const int lq = lane >> 3, lr = lane & 7;                                  \
    const uint32_t a_ku = (uint32_t)(lq >> 1);                                \
    const uint32_t b_ku = (uint32_t)(lq & 1);                                 \
    uint32_t a_off[4], a_swz[4], b_off[2], b_swz[2];                          \
    _Pragma("unroll")                                                         \
    for (int mt = 0; mt < 4; mt++) {                                          \
        const int row = wm + mt * 16 + ((lq & 1) << 3) + lr;                  \
        a_off[mt] = (uint32_t)(row * 128);                                    \
        a_swz[mt] = (uint32_t)(row & 7);                                      \
    }                                                                         \
    _Pragma("unroll")                                                         \
    for (int p = 0; p < 2; p++) {                                             \
        const int n = wn + (2 * p + (lq >> 1)) * 8 + lr;                      \
        b_off[p] = (uint32_t)(n * 128);                                       \
        b_swz[p] = (uint32_t)(n & 7);                                         \
    }                                                                         \
    auto load_tile = [&](int kt, int buf) {                                   \
        const uint32_t ab = sb + buf * STAGE;                                 \
        const uint32_t bb = ab + ASZ;                                         \
        const int k0 = kt * BKH;                                              \
        _Pragma("unroll")                                                     \
        for (int i = 0; i < 4; i++) {                                         \
            const int c = tid + i * 256;                                      \
            const int m = c >> 3, j = c & 7;                                  \
            cp16(ab + (uint32_t)(m * 128 + ((j ^ (m & 7)) << 4)),             \
                 (ASRC_EXPR) + k0 + j * 8);                                   \
        }                                                                     \
        _Pragma("unroll")                                                     \
        for (int i = 0; i < 4; i++) {                                         \
            const int c = tid + i * 256;                                      \
            const int n = c >> 3, j = c & 7;                                  \
            cp16(bb + (uint32_t)(n * 128 + ((j ^ (n & 7)) << 4)),             \
                 (BSRC_PTR) + (size_t)(n0 + n) * DIM + k0 + j * 8);           \
        }                                                                     \
        CP_COMMIT();                                                          \
    };                                                                        \
    float acc[4][4][4] = {};                                                  \
    load_tile(0, 0);                                                          \
    load_tile(1, 1);                                                          \
    for (int kt = 0; kt < KT; kt++) {                                         \
        if (kt == KT - 1) CP_WAIT0(); else CP_WAIT1();                        \
        __syncthreads();                                                      \
        if (kt + 2 < KT) load_tile(kt + 2, (kt + 2) % NSTAGE);                \
        const uint32_t ab = sb + (kt % NSTAGE) * STAGE;                       \
        const uint32_t bb = ab + ASZ;                                         \
        _Pragma("unroll")                                                     \
        for (int ks = 0; ks < 4; ks++) {                                      \
            uint32_t af[4][4], bf[4][2];                                      \
            const uint32_t ja = (uint32_t)(2 * ks) + a_ku;                    \
            const uint32_t jb = (uint32_t)(2 * ks) + b_ku;                    \
            _Pragma("unroll")                                                 \
            for (int mt = 0; mt < 4; mt++)                                    \
                ldsm_x4(af[mt][0], af[mt][1], af[mt][2], af[mt][3],           \
                        ab + a_off[mt] + ((ja ^ a_swz[mt]) << 4));            \
            _Pragma("unroll")                                                 \
            for (int p = 0; p < 2; p++)                                       \
                ldsm_x4(bf[2 * p][0], bf[2 * p][1],                           \
                        bf[2 * p + 1][0], bf[2 * p + 1][1],                   \
                        bb + b_off[p] + ((jb ^ b_swz[p]) << 4));              \
            _Pragma("unroll")                                                 \
            for (int mt = 0; mt < 4; mt++)                                    \
                _Pragma("unroll")                                             \
                for (int nt = 0; nt < 4; nt++)                                \
                    mma_f16(acc[mt][nt], af[mt], bf[nt]);                     \
        }                                                                     \
    }

// ---------------------------------------------------------------------------
// Kernel 1: QKV GEMM + bias + activation -> g_qkvh fp16
// ---------------------------------------------------------------------------
__global__ __launch_bounds__(256, 2) void gemm_qkv_tc(
    const float* __restrict__ bias)
{
    GEMM_BODY(g_xh + (size_t)(m0 + m) * DIM, g_wqT)

    const int region = n0 / DIM;   // 0=q, 1=k, 2=v  (128 | 768)
    const float qsc = 0.125f;
#pragma unroll
    for (int mt = 0; mt < 4; mt++) {
        const int r0 = m0 + wm + mt * 16 + gid;
#pragma unroll
        for (int nt = 0; nt < 4; nt++) {
            const int cidx = n0 + wn + nt * 8 + 2 * tig;
            const float b0 = bias[cidx], b1 = bias[cidx + 1];
            float v0 = acc[mt][nt][0] + b0, v1 = acc[mt][nt][1] + b1;
            float v2 = acc[mt][nt][2] + b0, v3 = acc[mt][nt][3] + b1;
            if (region == 0) {
                v0 = fmaxf(v0, 0.f) * qsc; v1 = fmaxf(v1, 0.f) * qsc;
                v2 = fmaxf(v2, 0.f) * qsc; v3 = fmaxf(v3, 0.f) * qsc;
            } else if (region == 1) {
                v0 = fmaxf(v0, 0.f); v1 = fmaxf(v1, 0.f);
                v2 = fmaxf(v2, 0.f); v3 = fmaxf(v3, 0.f);
            }
            *(half2*)(g_qkvh + (size_t)r0 * QKV_N + cidx)       = __floats2half2_rn(v0, v1);
            *(half2*)(g_qkvh + (size_t)(r0 + 8) * QKV_N + cidx) = __floats2half2_rn(v2, v3);
        }
    }
}

// ---------------------------------------------------------------------------
// Kernel 5: projection GEMM.  out[M,768] = convT @ wpT^T + b  (fp32 out)
// ---------------------------------------------------------------------------
__global__ __launch_bounds__(256, 2) void gemm_proj_tc(
    const float* __restrict__ bias, float* __restrict__ out)
{
    GEMM_BODY(g_convT + (size_t)(m0 + m) * DIM, g_wpT)

#pragma unroll
    for (int mt = 0; mt < 4; mt++) {
        const int r0 = m0 + wm + mt * 16 + gid;
#pragma unroll
        for (int nt = 0; nt < 4; nt++) {
            const int cidx = n0 + wn + nt * 8 + 2 * tig;
            const float b0 = bias[cidx], b1 = bias[cidx + 1];
            *(float2*)(out + (size_t)r0 * DIM + cidx) =
                make_float2(acc[mt][nt][0] + b0, acc[mt][nt][1] + b1);
            *(float2*)(out + (size_t)(r0 + 8) * DIM + cidx) =
                make_float2(acc[mt][nt][2] + b0, acc[mt][nt][3] + b1);
        }
    }
}

// ---------------------------------------------------------------------------
// Kernel 2a: partial context = k^T @ v over a 448-row slice (fp16 in, fp32 acc)
// ---------------------------------------------------------------------------
__global__ __launch_bounds__(256) void ctx_part_kernel()
{
    const int bh = blockIdx.x;
    const int sp = blockIdx.y;
    const int b = bh / HEADS, h = bh % HEADS;

    __shared__ float ks[32][64];
    __shared__ float vs[32][64];

    const int tid = threadIdx.x;
    const int ti = (tid >> 4) * 4;
    const int tj = (tid & 15) * 4;

    const size_t base = (size_t)b * SEQ * QKV_N + (size_t)h * HD;
    const int nstart = sp * CROWS;

    float acc[4][4] = {};

    for (int n0 = nstart; n0 < nstart + CROWS; n0 += 32) {
#pragma unroll
        for (int s = 0; s < 2; s++) {
            const int idx = tid + s * 256;
            const int r = idx >> 4;
            const int c4 = (idx & 15) * 4;
            const size_t rowb = base + (size_t)(n0 + r) * QKV_N;
            const __half* kp = g_qkvh + rowb + DIM + c4;
            const __half* vp = g_qkvh + rowb + 2 * DIM + c4;
            float2 k0 = __half22float2(*(const half2*)(kp));
            float2 k1 = __half22float2(*(const half2*)(kp + 2));
            float2 v0 = __half22float2(*(const half2*)(vp));
            float2 v1 = __half22float2(*(const half2*)(vp + 2));
            *(float4*)&ks[r][c4] = make_float4(k0.x, k0.y, k1.x, k1.y);
            *(float4*)&vs[r][c4] = make_float4(v0.x, v0.y, v1.x, v1.y);
        }
        __syncthreads();

#pragma unroll 8
        for (int nn = 0; nn < 32; nn++) {
            float kr[4], vr[4];
            *(float4*)kr = *(const float4*)&ks[nn][ti];
            *(float4*)vr = *(const float4*)&vs[nn][tj];
#pragma unroll
            for (int i = 0; i < 4; i++)
#pragma unroll
                for (int j = 0; j < 4; j++)
                    acc[i][j] = fmaf(kr[i], vr[j], acc[i][j]);
        }
        __syncthreads();
    }

    float* cb = g_ctxp + ((size_t)sp * BATCH * HEADS + bh) * HD * HD;
#pragma unroll
    for (int i = 0; i < 4; i++)
        *(float4*)&cb[(ti + i) * HD + tj] = *(float4*)(acc[i]);
}

__global__ __launch_bounds__(256) void ctx_reduce_kernel()
{
    const int bh = blockIdx.x;
    const int tid = threadIdx.x;
    const size_t off = (size_t)bh * HD * HD;
#pragma unroll
    for (int s = 0; s < 4; s++) {
        const int e4 = (tid + s * 256) * 4;
        float4 a = *(const float4*)(g_ctxp + off + e4);
#pragma unroll
        for (int p = 1; p < CSPLIT; p++) {
            const float4 b = *(const float4*)(g_ctxp + (size_t)p * BATCH * HEADS * HD * HD + off + e4);
            a.x += b.x; a.y += b.y; a.z += b.z; a.w += b.w;
        }
        *(float4*)(g_ctx + off + e4) = a;
    }
}

// ---------------------------------------------------------------------------
// Kernel 3: apply q @ ctx -> g_attnh [B,C,N] fp16
// ---------------------------------------------------------------------------
__global__ __launch_bounds__(256) void apply_kernel()
{
    const int bh = blockIdx.y;
    const int n0 = blockIdx.x * 64;
    const int b = bh / HEADS, h = bh % HEADS;

    __shared__ float cs[64][64];

    const int tid = threadIdx.x;
    const float* cb = g_ctx + (size_t)bh * 4096;
#pragma unroll
    for (int s = 0; s < 4; s++) {
        const int idx = tid + s * 256;
        const int r = idx >> 4;
        const int c4 = (idx & 15) * 4;
        *(float4*)&cs[r][c4] = *(const float4*)(cb + r * 64 + c4);
    }
    __syncthreads();

    const int tn = tid & 63;
    const int tg = (tid >> 6) * 16;

    const __half* qrow = g_qkvh + (size_t)(b * SEQ + n0 + tn) * QKV_N + (size_t)h * HD;

    float acc[16] = {};
#pragma unroll
    for (int d4 = 0; d4 < 16; d4++) {
        const __half* qp = qrow + d4 * 4;
        float2 qa = __half22float2(*(const half2*)(qp));
        float2 qb = __half22float2(*(const half2*)(qp + 2));
        const float qs[4] = {qa.x, qa.y, qb.x, qb.y};
#pragma unroll
        for (int u = 0; u < 4; u++) {
            const int dd = d4 * 4 + u;
            const float4 c0 = *(const float4*)&cs[dd][tg];
            const float4 c1 = *(const float4*)&cs[dd][tg + 4];
            const float4 c2 = *(const float4*)&cs[dd][tg + 8];
            const float4 c3 = *(const float4*)&cs[dd][tg + 12];
            acc[0]  = fmaf(qs[u], c0.x, acc[0]);  acc[1]  = fmaf(qs[u], c0.y, acc[1]);
            acc[2]  = fmaf(qs[u], c0.z, acc[2]);  acc[3]  = fmaf(qs[u], c0.w, acc[3]);
            acc[4]  = fmaf(qs[u], c1.x, acc[4]);  acc[5]  = fmaf(qs[u], c1.y, acc[5]);
            acc[6]  = fmaf(qs[u], c1.z, acc[6]);  acc[7]  = fmaf(qs[u], c1.w, acc[7]);
            acc[8]  = fmaf(qs[u], c2.x, acc[8]);  acc[9]  = fmaf(qs[u], c2.y, acc[9]);
            acc[10] = fmaf(qs[u], c2.z, acc[10]); acc[11] = fmaf(qs[u], c2.w, acc[11]);
            acc[12] = fmaf(qs[u], c3.x, acc[12]); acc[13] = fmaf(qs[u], c3.y, acc[13]);
            acc[14] = fmaf(qs[u], c3.z, acc[14]); acc[15] = fmaf(qs[u], c3.w, acc[15]);
        }
    }

    __half* ob = g_attnh + (size_t)b * DIM * SEQ + (size_t)(h * HD) * SEQ + n0 + tn;
#pragma unroll
    for (int j = 0; j < 16; j++)
        ob[(size_t)(tg + j) * SEQ] = __float2half_rn(acc[j]);
}

// ---------------------------------------------------------------------------
// Kernel 4: depthwise 3x3 conv (fp16 in, fp32 math, fp16 out [B,C,N])
// ---------------------------------------------------------------------------
__global__ __launch_bounds__(256) void dwconv_kernel(
    const float* __restrict__ w, const float* __restrict__ bias)
{
    const int bc = blockIdx.x;
    const int c = bc % DIM;

    __shared__ float sm[58 * 58];

    const int tid = threadIdx.x;
    for (int i = tid; i < 58 * 58; i += 256) sm[i] = 0.f;
    __syncthreads();

    const __half* ib = g_attnh + (size_t)bc * SEQ;
    for (int i = tid; i < SEQ; i += 256) {
        const int y = i / HWIMG, x = i - y * HWIMG;
        sm[(y + 1) * 58 + x + 1] = __half2float(ib[i]);
    }
    __syncthreads();

    const float* wc = w + c * 9;
    const float w0 = wc[0], w1 = wc[1], w2 = wc[2];
    const float w3 = wc[3], w4 = wc[4], w5 = wc[5];
    const float w6 = wc[6], w7 = wc[7], w8 = wc[8];
    const float bb = bias[c];

    __half* ob = g_convh + (size_t)bc * SEQ;
    for (int q = tid; q < 784; q += 256) {       // 784 = 56 rows * 14 quads
        const int y = q / 14;
        const int xq = (q - y * 14) * 4;
        const float* p0 = &sm[y * 58 + xq];
        const float* p1 = p0 + 58;
        const float* p2 = p0 + 116;
        float r0[6], r1[6], r2[6];
#pragma unroll
        for (int t = 0; t < 6; t++) { r0[t] = p0[t]; r1[t] = p1[t]; r2[t] = p2[t]; }
        float4 o;
        o.x = bb; o.y = bb; o.z = bb; o.w = bb;
        o.x = fmaf(w0, r0[0], o.x); o.x = fmaf(w1, r0[1], o.x); o.x = fmaf(w2, r0[2], o.x);
        o.x = fmaf(w3, r1[0], o.x); o.x = fmaf(w4, r1[1], o.x); o.x = fmaf(w5, r1[2], o.x);
        o.x = fmaf(w6, r2[0], o.x); o.x = fmaf(w7, r2[1], o.x); o.x = fmaf(w8, r2[2], o.x);
        o.y = fmaf(w0, r0[1], o.y); o.y = fmaf(w1, r0[2], o.y); o.y = fmaf(w2, r0[3], o.y);
        o.y = fmaf(w3, r1[1], o.y); o.y = fmaf(w4, r1[2], o.y); o.y = fmaf(w5, r1[3], o.y);
        o.y = fmaf(w6, r2[1], o.y); o.y = fmaf(w7, r2[2], o.y); o.y = fmaf(w8, r2[3], o.y);
        o.z = fmaf(w0, r0[2], o.z); o.z = fmaf(w1, r0[3], o.z); o.z = fmaf(w2, r0[4], o.z);
        o.z = fmaf(w3, r1[2], o.z); o.z = fmaf(w4, r1[3], o.z); o.z = fmaf(w5, r1[4], o.z);
        o.z = fmaf(w6, r2[2], o.z); o.z = fmaf(w7, r2[3], o.z); o.z = fmaf(w8, r2[4], o.z);
        o.w = fmaf(w0, r0[3], o.w); o.w = fmaf(w1, r0[4], o.w); o.w = fmaf(w2, r0[5], o.w);
        o.w = fmaf(w3, r1[3], o.w); o.w = fmaf(w4, r1[4], o.w); o.w = fmaf(w5, r1[5], o.w);
        o.w = fmaf(w6, r2[3], o.w); o.w = fmaf(w7, r2[4], o.w); o.w = fmaf(w8, r2[5], o.w);
        half2* op = (half2*)(ob + y * HWIMG + xq);
        op[0] = __floats2half2_rn(o.x, o.y);
        op[1] = __floats2half2_rn(o.z, o.w);
    }
}

// ---------------------------------------------------------------------------
// Kernel 4b: transpose conv fp16 [B,C,N] -> [M,C]  (64x64 tiles)
// ---------------------------------------------------------------------------
__global__ __launch_bounds__(256) void conv_transpose_kernel()
{
    __shared__ __half sm[64 * 66];
    const int nt = blockIdx.x;      // 0..48
    const int ct = blockIdx.y;      // 0..11
    const int b  = blockIdx.z;
    const int tid = threadIdx.x;

#pragma unroll
    for (int i = 0; i < 8; i++) {
        const int li = i * 256 + tid;       // over 64c x 32 half2-n
        const int c = li >> 5, n2 = li & 31;
        half2 v = *(const half2*)&g_convh[((size_t)(b * DIM + ct * 64 + c)) * SEQ + nt * 64 + 2 * n2];
        *(half2*)&sm[c * 66 + 2 * n2] = v;
    }
    __syncthreads();
#pragma unroll
    for (int i = 0; i < 8; i++) {
        const int li = i * 256 + tid;       // over 64n x 32 half2-c
        const int n = li >> 5, c2 = li & 31;
        half2 v = __halves2half2(sm[(2 * c2) * 66 + n], sm[(2 * c2 + 1) * 66 + n]);
        *(half2*)&g_convT[((size_t)(b * SEQ + nt * 64 + n)) * DIM + ct * 64 + 2 * c2] = v;
    }
}

// ---------------------------------------------------------------------------
extern "C" void kernel_launch(void* const* d_in, const int* in_sizes, int n_in,
                              void* d_out, int out_size)
{
    (void)in_sizes; (void)n_in; (void)out_size;
    const float* x      = (const float*)d_in[0];
    const float* qkv_w  = (const float*)d_in[1];
    const float* qkv_b  = (const float*)d_in[2];
    const float* dw_w   = (const float*)d_in[3];
    const float* dw_b   = (const float*)d_in[4];
    const float* proj_w = (const float*)d_in[5];
    const float* proj_b = (const float*)d_in[6];
    float* out = (float*)d_out;

    cudaFuncSetAttribute(gemm_qkv_tc, cudaFuncAttributeMaxDynamicSharedMemorySize, SMEM_DYN);
    cudaFuncSetAttribute(gemm_proj_tc, cudaFuncAttributeMaxDynamicSharedMemorySize, SMEM_DYN);

    __half* wq_p;  cudaGetSymbolAddress((void**)&wq_p, g_wqT);
    __half* wp_p;  cudaGetSymbolAddress((void**)&wp_p, g_wpT);

    const int nxh = (int)((size_t)M_TOTAL * DIM / 2);
    conv_x_f16<<<(nxh + 255) / 256, 256>>>(x);
    transpose_w_f16<<<((DIM / 2) * QKV_N + 255) / 256, 256>>>(qkv_w, wq_p, QKV_N);
    transpose_w_f16<<<((DIM / 2) * DIM + 255) / 256, 256>>>(proj_w, wp_p, DIM);

    gemm_qkv_tc<<<dim3(QKV_N / BN, M_TOTAL / BM), 256, SMEM_DYN>>>(qkv_b);
    ctx_part_kernel<<<dim3(BATCH * HEADS, CSPLIT), 256>>>();
    ctx_reduce_kernel<<<BATCH * HEADS, 256>>>();
    apply_kernel<<<dim3(SEQ / 64, BATCH * HEADS), 256>>>();
    dwconv_kernel<<<BATCH * DIM, 256>>>(dw_w, dw_b);
    conv_transpose_kernel<<<dim3(SEQ / 64, DIM / 64, BATCH), 256>>>();
    gemm_proj_tc<<<dim3(DIM / BN, M_TOTAL / BM), 256, SMEM_DYN>>>(proj_b, out);
}

// round 15
// speedup vs baseline: 1.6199x; 1.6199x over previous
#include <cuda_runtime.h>
#include <cuda_fp16.h>
#include <cstdint>
#include <cstddef>

#define DIM   768
#define HEADS 12
#define HD    64
#define BATCH 16
#define SEQ   3136
#define HWIMG 56
#define M_TOTAL (BATCH * SEQ)   /* 50176 */
#define QKV_N   (3 * DIM)       /* 2304  */

// GEMM tiling (mma.sync fp16 m16n8k16): 128x128x64, 256 threads,
// warp tile 64x32, 2 CTAs/SM, 3-stage cp.async pipeline.
#define BM 128
#define BN 128
#define BKH 64                  /* 64 halves = 128B rows */
#define KT (DIM / BKH)          /* 12 */
#define ASZ (BM * BKH * 2)      /* 16KB */
#define BSZ (BN * BKH * 2)      /* 16KB */
#define STAGE (ASZ + BSZ)       /* 32KB */
#define NSTAGE 3
#define SMEM_DYN (NSTAGE * STAGE)   /* 96KB */

#define CSPLIT 14               /* ctx N-split: 3136 = 14 * 224 */
#define CROWS  (SEQ / CSPLIT)   /* 224 */

// ---------------- scratch (static device allocations; no cudaMalloc) -------
__device__ float  g_qkv[(size_t)M_TOTAL * QKV_N];         // [M, 3C] fp32, activated
__device__ float  g_ctx[(size_t)BATCH * HEADS * HD * HD];
__device__ float  g_ctxp[(size_t)CSPLIT * BATCH * HEADS * HD * HD];
__device__ float  g_attn[(size_t)BATCH * DIM * SEQ];      // [B, C, N] fp32
__device__ __half g_convh[(size_t)BATCH * DIM * SEQ];     // conv out [B, C, N] fp16
__device__ __half g_convT[(size_t)M_TOTAL * DIM];         // conv out [M, C] fp16
__device__ __half g_xh[(size_t)M_TOTAL * DIM];            // x fp16 [M, K]
__device__ __half g_wqT[(size_t)QKV_N * DIM];             // qkv_w^T fp16 [N, K]
__device__ __half g_wpT[(size_t)DIM * DIM];               // proj_w^T fp16 [N, K]

// ---------------------------- PTX helpers ----------------------------------
__device__ __forceinline__ uint32_t cvta_smem(const void* p) {
    uint32_t a;
    asm("{ .reg .u64 t; cvta.to.shared.u64 t, %1; cvt.u32.u64 %0, t; }"
        : "=r"(a) : "l"(p));
    return a;
}

__device__ __forceinline__ void cp16(uint32_t dst, const void* src) {
    asm volatile("cp.async.cg.shared.global [%0], [%1], 16;"
                 :: "r"(dst), "l"(src) : "memory");
}
#define CP_COMMIT() asm volatile("cp.async.commit_group;" ::: "memory")
#define CP_WAIT1()  asm volatile("cp.async.wait_group 1;" ::: "memory")
#define CP_WAIT0()  asm volatile("cp.async.wait_group 0;" ::: "memory")

__device__ __forceinline__ uint32_t lds_u32(uint32_t addr) {
    uint32_t v;
    asm volatile("ld.shared.b32 %0, [%1];" : "=r"(v) : "r"(addr));
    return v;
}

__device__ __forceinline__ void mma_f16(float* c, const uint32_t* a, const uint32_t* b) {
    asm volatile(
        "mma.sync.aligned.m16n8k16.row.col.f32.f16.f16.f32 "
        "{%0,%1,%2,%3}, {%4,%5,%6,%7}, {%8,%9}, {%0,%1,%2,%3};"
        : "+f"(c[0]), "+f"(c[1]), "+f"(c[2]), "+f"(c[3])
        : "r"(a[0]), "r"(a[1]), "r"(a[2]), "r"(a[3]), "r"(b[0]), "r"(b[1]));
}

// ---------------------------------------------------------------------------
// Prepass A: x fp32 -> fp16 (half2 stores)
// ---------------------------------------------------------------------------
__global__ __launch_bounds__(256) void conv_x_f16(const float* __restrict__ in)
{
    const size_t i = (size_t)blockIdx.x * 256 + threadIdx.x;   // half2 index
    if (i < (size_t)M_TOTAL * DIM / 2) {
        float2 v = ((const float2*)in)[i];
        ((half2*)g_xh)[i] = __float22half2_rn(v);
    }
}

// Prepass B: weight fp32 [K,N] -> fp16 [N,K] (coalesced reads, half2 writes)
__global__ __launch_bounds__(256) void transpose_w_f16(
    const float* __restrict__ W, __half* __restrict__ out, int N)
{
    const int i = blockIdx.x * 256 + threadIdx.x;   // over (K/2) * N
    if (i < (DIM / 2) * N) {
        const int n = i % N, k2 = i / N;
        float a = W[(size_t)(2 * k2) * N + n];
        float b = W[(size_t)(2 * k2 + 1) * N + n];
        *(half2*)&out[(size_t)n * DIM + 2 * k2] = __floats2half2_rn(a, b);
    }
}

// ---------------------------------------------------------------------------
// fp16 GEMM core (shared by qkv + proj): C[M,N] = Ah[M,K] @ BhT[N,K]^T
// A smem: [m][64 halves] 128B rows, 16B-unit swizzle j' = j ^ (m&7).
// B smem: [n][64 halves] same swizzle on n.
// Fragment u32 addr: row*32 + (kp ^ ((row&7)<<2)), kp in 0..31.
// ---------------------------------------------------------------------------
#define GEMM_BODY(ASRC_EXPR, BSRC_PTR)                                        \
    extern __shared__ char smem[];                                            \
    const uint32_t sb = cvta_smem(smem);                                      \
    const int tid  = threadIdx.x;                                             \
    const int wid  = tid >> 5, lane = tid & 31;                               \
    const int gid  = lane >> 2, tig = lane & 3;                               \
    const int m0 = blockIdx.y * BM, n0 = blockIdx.x * BN;                     \
    const int wm = (wid & 1) * 64, wn = (wid >> 1) * 32;                      \
    auto load_tile = [&](int kt, int buf) {                                   \
        const uint32_t ab = sb + buf * STAGE;                                 \
        const uint32_t bb = ab + ASZ;                                         \
        const int k0 = kt * BKH;                                              \
        _Pragma("unroll")                                                     \
        for (int i = 0; i < 4; i++) {                                         \
            const int c = tid + i * 256;                                      \
            const int m = c >> 3, j = c & 7;                                  \
            cp16(ab + (uint32_t)(m * 128 + ((j ^ (m & 7)) << 4)),             \
                 (ASRC_EXPR) + k0 + j * 8);                                   \
        }                                                                     \
        _Pragma("unroll")                                                     \
        for (int i = 0; i < 4; i++) {                                         \
            const int c = tid + i * 256;                                      \
            const int n = c >> 3, j = c & 7;                                  \
            cp16(bb + (uint32_t)(n * 128 + ((j ^ (n & 7)) << 4)),             \
                 (BSRC_PTR) + (size_t)(n0 + n) * DIM + k0 + j * 8);           \
        }                                                                     \
        CP_COMMIT();                                                          \
    };                                                                        \
    float acc[4][4][4] = {};                                                  \
    load_tile(0, 0);                                                          \
    load_tile(1, 1);                                                          \
    for (int kt = 0; kt < KT; kt++) {                                         \
        if (kt == KT - 1) CP_WAIT0(); else CP_WAIT1();                        \
        __syncthreads();                                                      \
        if (kt + 2 < KT) load_tile(kt + 2, (kt + 2) % NSTAGE);                \
        const uint32_t ab = sb + (kt % NSTAGE) * STAGE;                       \
        const uint32_t bb = ab + ASZ;                                         \
        _Pragma("unroll")                                                     \
        for (int ks = 0; ks < 4; ks++) {                                      \
            const int kp = ks * 8 + tig;                                      \
            uint32_t af[4][4], bf[4][2];                                      \
            _Pragma("unroll")                                                 \
            for (int mt = 0; mt < 4; mt++) {                                  \
                const int m  = wm + mt * 16 + gid;    /* m&7 == gid */        \
                const int m8 = m + 8;                                         \
                const uint32_t sw = (uint32_t)(gid << 2);                     \
                af[mt][0] = lds_u32(ab + ((uint32_t)(m  * 32) + ((uint32_t)kp ^ sw)) * 4);       \
                af[mt][1] = lds_u32(ab + ((uint32_t)(m8 * 32) + ((uint32_t)kp ^ sw)) * 4);       \
                af[mt][2] = lds_u32(ab + ((uint32_t)(m  * 32) + ((uint32_t)(kp + 4) ^ sw)) * 4); \
                af[mt][3] = lds_u32(ab + ((uint32_t)(m8 * 32) + ((uint32_t)(kp + 4) ^ sw)) * 4); \
            }                                                                 \
            _Pragma("unroll")                                                 \
            for (int nt = 0; nt < 4; nt++) {                                  \
                const int n = wn + nt * 8 + gid;      /* n&7 == gid */        \
                const uint32_t sw = (uint32_t)(gid << 2);                     \
                bf[nt][0] = lds_u32(bb + ((uint32_t)(n * 32) + ((uint32_t)kp ^ sw)) * 4);        \
                bf[nt][1] = lds_u32(bb + ((uint32_t)(n * 32) + ((uint32_t)(kp + 4) ^ sw)) * 4);  \
            }                                                                 \
            _Pragma("unroll")                                                 \
            for (int mt = 0; mt < 4; mt++)                                    \
                _Pragma("unroll")                                             \
                for (int nt = 0; nt < 4; nt++)                                \
                    mma_f16(acc[mt][nt], af[mt], bf[nt]);                     \
        }                                                                     \
    }

// ---------------------------------------------------------------------------
// Kernel 1: QKV GEMM + bias + activation -> g_qkv fp32
// ---------------------------------------------------------------------------
__global__ __launch_bounds__(256, 2) void gemm_qkv_tc(
    const float* __restrict__ bias)
{
    GEMM_BODY(g_xh + (size_t)(m0 + m) * DIM, g_wqT)

    const int region = n0 / DIM;   // 0=q, 1=k, 2=v  (128 | 768)
    const float qsc = 0.125f;
#pragma unroll
    for (int mt = 0; mt < 4; mt++) {
        const int r0 = m0 + wm + mt * 16 + gid;
#pragma unroll
        for (int nt = 0; nt < 4; nt++) {
            const int cidx = n0 + wn + nt * 8 + 2 * tig;
            const float b0 = bias[cidx], b1 = bias[cidx + 1];
            float v0 = acc[mt][nt][0] + b0, v1 = acc[mt][nt][1] + b1;
            float v2 = acc[mt][nt][2] + b0, v3 = acc[mt][nt][3] + b1;
            if (region == 0) {
                v0 = fmaxf(v0, 0.f) * qsc; v1 = fmaxf(v1, 0.f) * qsc;
                v2 = fmaxf(v2, 0.f) * qsc; v3 = fmaxf(v3, 0.f) * qsc;
            } else if (region == 1) {
                v0 = fmaxf(v0, 0.f); v1 = fmaxf(v1, 0.f);
                v2 = fmaxf(v2, 0.f); v3 = fmaxf(v3, 0.f);
            }
            *(float2*)(g_qkv + (size_t)r0 * QKV_N + cidx)       = make_float2(v0, v1);
            *(float2*)(g_qkv + (size_t)(r0 + 8) * QKV_N + cidx) = make_float2(v2, v3);
        }
    }
}

// ---------------------------------------------------------------------------
// Kernel 5: projection GEMM.  out[M,768] = convT @ wpT^T + b
// ---------------------------------------------------------------------------
__global__ __launch_bounds__(256, 2) void gemm_proj_tc(
    const float* __restrict__ bias, float* __restrict__ out)
{
    GEMM_BODY(g_convT + (size_t)(m0 + m) * DIM, g_wpT)

#pragma unroll
    for (int mt = 0; mt < 4; mt++) {
        const int r0 = m0 + wm + mt * 16 + gid;
#pragma unroll
        for (int nt = 0; nt < 4; nt++) {
            const int cidx = n0 + wn + nt * 8 + 2 * tig;
            const float b0 = bias[cidx], b1 = bias[cidx + 1];
            *(float2*)(out + (size_t)r0 * DIM + cidx) =
                make_float2(acc[mt][nt][0] + b0, acc[mt][nt][1] + b1);
            *(float2*)(out + (size_t)(r0 + 8) * DIM + cidx) =
                make_float2(acc[mt][nt][2] + b0, acc[mt][nt][3] + b1);
        }
    }
}

// ---------------------------------------------------------------------------
// Kernel 2a: partial context = k^T @ v over a 224-row slice -> [64,64].
// grid (192 bh, 14 splits)
// ---------------------------------------------------------------------------
__global__ __launch_bounds__(256) void ctx_part_kernel()
{
    const int bh = blockIdx.x;
    const int sp = blockIdx.y;
    const int b = bh / HEADS, h = bh % HEADS;

    __shared__ float ks[32][64];
    __shared__ float vs[32][64];

    const int tid = threadIdx.x;
    const int ti = (tid >> 4) * 4;
    const int tj = (tid & 15) * 4;

    const size_t base = (size_t)b * SEQ * QKV_N + (size_t)h * HD;
    const int nstart = sp * CROWS;

    float acc[4][4] = {};

    for (int n0 = nstart; n0 < nstart + CROWS; n0 += 32) {
#pragma unroll
        for (int s = 0; s < 2; s++) {
            const int idx = tid + s * 256;
            const int r = idx >> 4;
            const int c4 = (idx & 15) * 4;
            const size_t rowb = base + (size_t)(n0 + r) * QKV_N;
            *(float4*)&ks[r][c4] = *(const float4*)(g_qkv + rowb + DIM + c4);
            *(float4*)&vs[r][c4] = *(const float4*)(g_qkv + rowb + 2 * DIM + c4);
        }
        __syncthreads();

#pragma unroll 8
        for (int nn = 0; nn < 32; nn++) {
            float kr[4], vr[4];
            *(float4*)kr = *(const float4*)&ks[nn][ti];
            *(float4*)vr = *(const float4*)&vs[nn][tj];
#pragma unroll
            for (int i = 0; i < 4; i++)
#pragma unroll
                for (int j = 0; j < 4; j++)
                    acc[i][j] = fmaf(kr[i], vr[j], acc[i][j]);
        }
        __syncthreads();
    }

    float* cb = g_ctxp + ((size_t)sp * BATCH * HEADS + bh) * HD * HD;
#pragma unroll
    for (int i = 0; i < 4; i++)
        *(float4*)&cb[(ti + i) * HD + tj] = *(float4*)(acc[i]);
}

// Kernel 2b: reduce 14 partials -> g_ctx.  192 blocks x 256 threads.
__global__ __launch_bounds__(256) void ctx_reduce_kernel()
{
    const int bh = blockIdx.x;
    const int tid = threadIdx.x;
    const size_t off = (size_t)bh * HD * HD;
#pragma unroll
    for (int s = 0; s < 4; s++) {
        const int e4 = (tid + s * 256) * 4;
        float4 a = *(const float4*)(g_ctxp + off + e4);
#pragma unroll
        for (int p = 1; p < CSPLIT; p++) {
            const float4 b = *(const float4*)(g_ctxp + (size_t)p * BATCH * HEADS * HD * HD + off + e4);
            a.x += b.x; a.y += b.y; a.z += b.z; a.w += b.w;
        }
        *(float4*)(g_ctx + off + e4) = a;
    }
}

// ---------------------------------------------------------------------------
// Kernel 3: apply q @ ctx -> g_attn [B,C,N] fp32
// ---------------------------------------------------------------------------
__global__ __launch_bounds__(256) void apply_kernel()
{
    const int bh = blockIdx.y;
    const int n0 = blockIdx.x * 64;
    const int b = bh / HEADS, h = bh % HEADS;

    __shared__ float cs[64][64];

    const int tid = threadIdx.x;
    const float* cb = g_ctx + (size_t)bh * 4096;
#pragma unroll
    for (int s = 0; s < 4; s++) {
        const int idx = tid + s * 256;
        const int r = idx >> 4;
        const int c4 = (idx & 15) * 4;
        *(float4*)&cs[r][c4] = *(const float4*)(cb + r * 64 + c4);
    }
    __syncthreads();

    const int tn = tid & 63;
    const int tg = (tid >> 6) * 16;

    const float* qrow = g_qkv + (size_t)(b * SEQ + n0 + tn) * QKV_N + (size_t)h * HD;

    float acc[16] = {};
#pragma unroll
    for (int d4 = 0; d4 < 16; d4++) {
        const float4 qv = *(const float4*)(qrow + d4 * 4);
        const float qs[4] = {qv.x, qv.y, qv.z, qv.w};
#pragma unroll
        for (int u = 0; u < 4; u++) {
            const int dd = d4 * 4 + u;
            const float4 c0 = *(const float4*)&cs[dd][tg];
            const float4 c1 = *(const float4*)&cs[dd][tg + 4];
            const float4 c2 = *(const float4*)&cs[dd][tg + 8];
            const float4 c3 = *(const float4*)&cs[dd][tg + 12];
            acc[0]  = fmaf(qs[u], c0.x, acc[0]);  acc[1]  = fmaf(qs[u], c0.y, acc[1]);
            acc[2]  = fmaf(qs[u], c0.z, acc[2]);  acc[3]  = fmaf(qs[u], c0.w, acc[3]);
            acc[4]  = fmaf(qs[u], c1.x, acc[4]);  acc[5]  = fmaf(qs[u], c1.y, acc[5]);
            acc[6]  = fmaf(qs[u], c1.z, acc[6]);  acc[7]  = fmaf(qs[u], c1.w, acc[7]);
            acc[8]  = fmaf(qs[u], c2.x, acc[8]);  acc[9]  = fmaf(qs[u], c2.y, acc[9]);
            acc[10] = fmaf(qs[u], c2.z, acc[10]); acc[11] = fmaf(qs[u], c2.w, acc[11]);
            acc[12] = fmaf(qs[u], c3.x, acc[12]); acc[13] = fmaf(qs[u], c3.y, acc[13]);
            acc[14] = fmaf(qs[u], c3.z, acc[14]); acc[15] = fmaf(qs[u], c3.w, acc[15]);
        }
    }

    float* ob = g_attn + (size_t)b * DIM * SEQ + (size_t)(h * HD) * SEQ + n0 + tn;
#pragma unroll
    for (int j = 0; j < 16; j++)
        ob[(size_t)(tg + j) * SEQ] = acc[j];
}

// ---------------------------------------------------------------------------
// Kernel 4: depthwise 3x3 conv; output fp16 [B,C,N]
// ---------------------------------------------------------------------------
__global__ __launch_bounds__(256) void dwconv_kernel(
    const float* __restrict__ w, const float* __restrict__ bias)
{
    const int bc = blockIdx.x;
    const int c = bc % DIM;

    __shared__ float sm[58 * 58];

    const int tid = threadIdx.x;
    for (int i = tid; i < 58 * 58; i += 256) sm[i] = 0.f;
    __syncthreads();

    const float* ib = g_attn + (size_t)bc * SEQ;
    for (int i = tid; i < SEQ; i += 256) {
        const int y = i / HWIMG, x = i - y * HWIMG;
        sm[(y + 1) * 58 + x + 1] = ib[i];
    }
    __syncthreads();

    const float* wc = w + c * 9;
    const float w0 = wc[0], w1 = wc[1], w2 = wc[2];
    const float w3 = wc[3], w4 = wc[4], w5 = wc[5];
    const float w6 = wc[6], w7 = wc[7], w8 = wc[8];
    const float bb = bias[c];

    __half* ob = g_convh + (size_t)bc * SEQ;
    for (int q = tid; q < 784; q += 256) {       // 784 = 56 rows * 14 quads
        const int y = q / 14;
        const int xq = (q - y * 14) * 4;
        const float* p0 = &sm[y * 58 + xq];
        const float* p1 = p0 + 58;
        const float* p2 = p0 + 116;
        float r0[6], r1[6], r2[6];
#pragma unroll
        for (int t = 0; t < 6; t++) { r0[t] = p0[t]; r1[t] = p1[t]; r2[t] = p2[t]; }
        float4 o;
        o.x = bb; o.y = bb; o.z = bb; o.w = bb;
        o.x = fmaf(w0, r0[0], o.x); o.x = fmaf(w1, r0[1], o.x); o.x = fmaf(w2, r0[2], o.x);
        o.x = fmaf(w3, r1[0], o.x); o.x = fmaf(w4, r1[1], o.x); o.x = fmaf(w5, r1[2], o.x);
        o.x = fmaf(w6, r2[0], o.x); o.x = fmaf(w7, r2[1], o.x); o.x = fmaf(w8, r2[2], o.x);
        o.y = fmaf(w0, r0[1], o.y); o.y = fmaf(w1, r0[2], o.y); o.y = fmaf(w2, r0[3], o.y);
        o.y = fmaf(w3, r1[1], o.y); o.y = fmaf(w4, r1[2], o.y); o.y = fmaf(w5, r1[3], o.y);
        o.y = fmaf(w6, r2[1], o.y); o.y = fmaf(w7, r2[2], o.y); o.y = fmaf(w8, r2[3], o.y);
        o.z = fmaf(w0, r0[2], o.z); o.z = fmaf(w1, r0[3], o.z); o.z = fmaf(w2, r0[4], o.z);
        o.z = fmaf(w3, r1[2], o.z); o.z = fmaf(w4, r1[3], o.z); o.z = fmaf(w5, r1[4], o.z);
        o.z = fmaf(w6, r2[2], o.z); o.z = fmaf(w7, r2[3], o.z); o.z = fmaf(w8, r2[4], o.z);
        o.w = fmaf(w0, r0[3], o.w); o.w = fmaf(w1, r0[4], o.w); o.w = fmaf(w2, r0[5], o.w);
        o.w = fmaf(w3, r1[3], o.w); o.w = fmaf(w4, r1[4], o.w); o.w = fmaf(w5, r1[5], o.w);
        o.w = fmaf(w6, r2[3], o.w); o.w = fmaf(w7, r2[4], o.w); o.w = fmaf(w8, r2[5], o.w);
        half2* op = (half2*)(ob + y * HWIMG + xq);
        op[0] = __floats2half2_rn(o.x, o.y);
        op[1] = __floats2half2_rn(o.z, o.w);
    }
}

// ---------------------------------------------------------------------------
// Kernel 4b: transpose conv fp16 [B,C,N] -> [M,C]  (64x64 tiles)
// ---------------------------------------------------------------------------
__global__ __launch_bounds__(256) void conv_transpose_kernel()
{
    __shared__ __half sm[64 * 66];
    const int nt = blockIdx.x;      // 0..48
    const int ct = blockIdx.y;      // 0..11
    const int b  = blockIdx.z;
    const int tid = threadIdx.x;

#pragma unroll
    for (int i = 0; i < 8; i++) {
        const int li = i * 256 + tid;       // over 64c x 32 half2-n
        const int c = li >> 5, n2 = li & 31;
        half2 v = *(const half2*)&g_convh[((size_t)(b * DIM + ct * 64 + c)) * SEQ + nt * 64 + 2 * n2];
        *(half2*)&sm[c * 66 + 2 * n2] = v;
    }
    __syncthreads();
#pragma unroll
    for (int i = 0; i < 8; i++) {
        const int li = i * 256 + tid;       // over 64n x 32 half2-c
        const int n = li >> 5, c2 = li & 31;
        half2 v = __halves2half2(sm[(2 * c2) * 66 + n], sm[(2 * c2 + 1) * 66 + n]);
        *(half2*)&g_convT[((size_t)(b * SEQ + nt * 64 + n)) * DIM + ct * 64 + 2 * c2] = v;
    }
}

// ---------------------------------------------------------------------------
extern "C" void kernel_launch(void* const* d_in, const int* in_sizes, int n_in,
                              void* d_out, int out_size)
{
    (void)in_sizes; (void)n_in; (void)out_size;
    const float* x      = (const float*)d_in[0];
    const float* qkv_w  = (const float*)d_in[1];
    const float* qkv_b  = (const float*)d_in[2];
    const float* dw_w   = (const float*)d_in[3];
    const float* dw_b   = (const float*)d_in[4];
    const float* proj_w = (const float*)d_in[5];
    const float* proj_b = (const float*)d_in[6];
    float* out = (float*)d_out;

    cudaFuncSetAttribute(gemm_qkv_tc, cudaFuncAttributeMaxDynamicSharedMemorySize, SMEM_DYN);
    cudaFuncSetAttribute(gemm_proj_tc, cudaFuncAttributeMaxDynamicSharedMemorySize, SMEM_DYN);

    __half* wq_p;  cudaGetSymbolAddress((void**)&wq_p, g_wqT);
    __half* wp_p;  cudaGetSymbolAddress((void**)&wp_p, g_wpT);

    const int nxh = (int)((size_t)M_TOTAL * DIM / 2);
    conv_x_f16<<<(nxh + 255) / 256, 256>>>(x);
    transpose_w_f16<<<((DIM / 2) * QKV_N + 255) / 256, 256>>>(qkv_w, wq_p, QKV_N);
    transpose_w_f16<<<((DIM / 2) * DIM + 255) / 256, 256>>>(proj_w, wp_p, DIM);

    gemm_qkv_tc<<<dim3(QKV_N / BN, M_TOTAL / BM), 256, SMEM_DYN>>>(qkv_b);
    ctx_part_kernel<<<dim3(BATCH * HEADS, CSPLIT), 256>>>();
    ctx_reduce_kernel<<<BATCH * HEADS, 256>>>();
    apply_kernel<<<dim3(SEQ / 64, BATCH * HEADS), 256>>>();
    dwconv_kernel<<<BATCH * DIM, 256>>>(dw_w, dw_b);
    conv_transpose_kernel<<<dim3(SEQ / 64, DIM / 64, BATCH), 256>>>();
    gemm_proj_tc<<<dim3(DIM / BN, M_TOTAL / BM), 256, SMEM_DYN>>>(proj_b, out);
}